// round 1
// baseline (speedup 1.0000x reference)
#include <cuda_runtime.h>
#include <cuda_bf16.h>
#include <math.h>

#define B_SZ 256
#define R_SZ 2048
#define D_SZ 64
#define K_TOP 20

// 2 MB scratch for cosine similarities [B, R]
__device__ float g_sims[B_SZ * R_SZ];

// ---------------------------------------------------------------------------
// Kernel 1: fused copy x->out + cosine similarity vs query row.
// Half-warp (16 lanes) per row, float4 per lane (64 floats/row).
// ---------------------------------------------------------------------------
__global__ __launch_bounds__(256) void sims_copy_kernel(
    const float* __restrict__ x,
    const int*   __restrict__ qrels,
    float*       __restrict__ out)
{
    const int warp = (blockIdx.x * blockDim.x + threadIdx.x) >> 5;
    const int lane = threadIdx.x & 31;
    const int half = lane >> 4;          // 0 or 1: which of the warp's 2 rows
    const int hl   = lane & 15;          // lane within half-warp

    const long long row = (long long)warp * 2 + half;   // global row < B*R
    const int b = (int)(row >> 11);                      // R = 2048
    const int r = (int)(row & (R_SZ - 1));
    const int qr = __ldg(&qrels[b]);

    const float4* vp = reinterpret_cast<const float4*>(x + row * D_SZ) + hl;
    const float4  v  = *vp;

    const long long qrow = ((long long)b * R_SZ + qr) * D_SZ;
    const float4* qp = reinterpret_cast<const float4*>(x + qrow) + hl;
    const float4  q  = __ldg(qp);

    // copy row to output (query rows get overwritten by kernel 2 later)
    reinterpret_cast<float4*>(out + row * D_SZ)[hl] = v;

    float dot = v.x * q.x + v.y * q.y + v.z * q.z + v.w * q.w;
    float ss  = v.x * v.x + v.y * v.y + v.z * v.z + v.w * v.w;
    float qs  = q.x * q.x + q.y * q.y + q.z * q.z + q.w * q.w;

    #pragma unroll
    for (int o = 8; o; o >>= 1) {
        dot += __shfl_xor_sync(0xffffffffu, dot, o);
        ss  += __shfl_xor_sync(0xffffffffu, ss,  o);
        qs  += __shfl_xor_sync(0xffffffffu, qs,  o);
    }

    if (hl == 0) {
        float nr = fmaxf(sqrtf(ss), 1e-12f);
        float nq = fmaxf(sqrtf(qs), 1e-12f);
        float s  = dot / (nr * nq);
        if (r == qr) s = -1.0f;          // exclude self
        g_sims[row] = s;
    }
}

// ---------------------------------------------------------------------------
// Kernel 2: per-batch top-20, weighting, and query-row rewrite.
// One block of 256 threads per batch element.
// ---------------------------------------------------------------------------
__device__ __forceinline__ unsigned packf(float f) {
    unsigned u = __float_as_uint(f);
    return (u & 0x80000000u) ? ~u : (u | 0x80000000u);
}
__device__ __forceinline__ float unpackf(unsigned p) {
    unsigned b = (p & 0x80000000u) ? (p ^ 0x80000000u) : ~p;
    return __uint_as_float(b);
}

__global__ __launch_bounds__(256) void topk_enhance_kernel(
    const float* __restrict__ x,
    const int*   __restrict__ qrels,
    const float* __restrict__ thr_raw_p,
    const float* __restrict__ str_raw_p,
    const float* __restrict__ wscale_p,
    const float* __restrict__ temp_p,
    float*       __restrict__ out)
{
    const int b   = blockIdx.x;
    const int tid = threadIdx.x;

    __shared__ float ssim[R_SZ];
    __shared__ unsigned long long sred[256];
    __shared__ float topv[K_TOP];
    __shared__ int   topi[K_TOP];
    __shared__ float rinv[K_TOP];
    __shared__ float adj[K_TOP];
    __shared__ float s_strength;
    __shared__ int   s_hasvalid;

    const float* simrow = g_sims + (long long)b * R_SZ;
    for (int j = tid; j < R_SZ; j += 256) ssim[j] = simrow[j];
    __syncthreads();

    // --- iterative top-20 (tie-break: smaller index wins, matching jax) ---
    for (int it = 0; it < K_TOP; ++it) {
        unsigned long long best = 0ull;
        #pragma unroll
        for (int j = tid; j < R_SZ; j += 256) {
            unsigned u = packf(ssim[j]);
            unsigned long long key =
                ((unsigned long long)u << 32) | (unsigned)(R_SZ - 1 - j);
            if (key > best) best = key;
        }
        sred[tid] = best;
        __syncthreads();
        #pragma unroll
        for (int o = 128; o; o >>= 1) {
            if (tid < o && sred[tid + o] > sred[tid]) sred[tid] = sred[tid + o];
            __syncthreads();
        }
        if (tid == 0) {
            unsigned long long k = sred[0];
            int idx  = (R_SZ - 1) - (int)(k & 0xffffffffu);
            topi[it] = idx;
            topv[it] = unpackf((unsigned)(k >> 32));
            ssim[idx] = -1e30f;
        }
        __syncthreads();
    }

    // --- norms of the 20 selected rows (warp w handles k = w, w+8, w+16) ---
    {
        const int wid = tid >> 5, lane = tid & 31;
        for (int k = wid; k < K_TOP; k += 8) {
            const float* rp = x + ((long long)b * R_SZ + topi[k]) * D_SZ;
            float2 v = reinterpret_cast<const float2*>(rp)[lane];
            float ssq = v.x * v.x + v.y * v.y;
            #pragma unroll
            for (int o = 16; o; o >>= 1) ssq += __shfl_xor_sync(0xffffffffu, ssq, o);
            if (lane == 0) rinv[k] = 1.0f / fmaxf(sqrtf(ssq), 1e-12f);
        }
    }
    __syncthreads();

    // --- scalar weighting pipeline (20 elems; single thread) ---
    if (tid == 0) {
        const float thr      = 1.0f / (1.0f + expf(-thr_raw_p[0]));
        const float strength = 0.2f / (1.0f + expf(-str_raw_p[0]));
        const float tempv    = fminf(fmaxf(temp_p[0], 0.1f), 10.0f);
        const float ws       = wscale_p[0];
        const int   qr       = qrels[b];

        float logits[K_TOP], ev[K_TOP];
        bool  valid[K_TOP];
        float m = -1e9f;
        #pragma unroll
        for (int k = 0; k < K_TOP; ++k) {
            valid[k]  = (topv[k] > thr) && (topi[k] != qr);
            logits[k] = valid[k] ? topv[k] / tempv : -1e9f;
            m = fmaxf(m, logits[k]);
        }
        float se = 0.0f;
        #pragma unroll
        for (int k = 0; k < K_TOP; ++k) { ev[k] = expf(logits[k] - m); se += ev[k]; }

        float suma = 0.0f;
        int hv = 0;
        #pragma unroll
        for (int k = 0; k < K_TOP; ++k) {
            float w  = valid[k] ? (ev[k] / se) : 0.0f;
            float sw = 1.0f / (1.0f + expf(-(topv[k] - thr) * 10.0f));
            float a  = w * sw * (1.0f + ws * topv[k]);
            adj[k] = a;
            suma  += a;
            hv |= (int)valid[k];
        }
        const float inv = 1.0f / (suma + 1e-8f);
        #pragma unroll
        for (int k = 0; k < K_TOP; ++k) adj[k] *= inv;

        s_strength = strength;
        s_hasvalid = hv;
    }
    __syncthreads();

    // --- weighted sum of normalized top rows + mix into query row ---
    if (tid < D_SZ) {
        const int qr = qrels[b];
        const long long qoff = ((long long)b * R_SZ + qr) * D_SZ;
        const float qo = x[qoff + tid];
        float acc = 0.0f;
        #pragma unroll
        for (int k = 0; k < K_TOP; ++k) {
            acc += (adj[k] * rinv[k]) * x[((long long)b * R_SZ + topi[k]) * D_SZ + tid];
        }
        const float s = s_strength;
        const float res = s_hasvalid ? (1.0f - s) * qo + s * acc : qo;
        out[qoff + tid] = res;
    }
}

// ---------------------------------------------------------------------------
extern "C" void kernel_launch(void* const* d_in, const int* in_sizes, int n_in,
                              void* d_out, int out_size)
{
    const float* x     = (const float*)d_in[0];
    const int*   qrels = (const int*)  d_in[1];
    const float* thr   = (const float*)d_in[2];
    const float* str   = (const float*)d_in[3];
    const float* wsc   = (const float*)d_in[4];
    const float* tmp   = (const float*)d_in[5];
    float* out = (float*)d_out;

    // Kernel 1: 2 rows/warp, 8 warps/block -> 16 rows/block
    const int total_rows = B_SZ * R_SZ;                  // 524288
    const int blocks1 = total_rows / 16;                 // 32768
    sims_copy_kernel<<<blocks1, 256>>>(x, qrels, out);

    // Kernel 2: one block per batch element
    topk_enhance_kernel<<<B_SZ, 256>>>(x, qrels, thr, str, wsc, tmp, out);
}